// round 1
// baseline (speedup 1.0000x reference)
#include <cuda_runtime.h>

#define B_ 64
#define C_ 64
#define T_ 4000
#define TCH 25           // T-chunks for gram kernel (4000/25 = 160 t per CTA)
#define TILE_T 32
#define TILES_PER 5      // 160 / 32
#define PADA 68          // smem row pad (floats) for gram tile
#define TC_C 160         // t-chunk width for apply kernel (25 chunks * 160 = 4000)
#define NCH_C 25

// Scratch (static device globals — allocation-free)
__device__ float g_gp[B_ * TCH * C_ * C_];   // partial Grams, 26.2 MB
__device__ float g_sxp[B_ * TCH * C_];       // partial channel sums
__device__ float g_at[B_ * C_ * C_];         // attention matrix M[r][s], row-major per batch

typedef unsigned long long u64t;

__device__ __forceinline__ u64t fdup(float a) {
    u64t r; asm("mov.b64 %0, {%1, %1};" : "=l"(r) : "f"(a)); return r;
}
__device__ __forceinline__ void ffma2(u64t& d, u64t a, u64t b) {
    asm("fma.rn.f32x2 %0, %1, %2, %0;" : "+l"(d) : "l"(a), "l"(b));
}
__device__ __forceinline__ float2 funp(u64t v) {
    float2 r; asm("mov.b64 {%0, %1}, %2;" : "=f"(r.x), "=f"(r.y) : "l"(v)); return r;
}

// ---------------------------------------------------------------------------
// Kernel A: partial Gram G[c][e] = sum_t x[c,t]*x[e,t] over this CTA's t-range,
// plus partial per-channel sums sx[c]. Grid (TCH, B_), 256 threads.
// Thread (ty,tx) in 16x16 grid owns 4x4 output tile, accumulated as f32x2 pairs.
// ---------------------------------------------------------------------------
__global__ void __launch_bounds__(256) k_gram(const float* __restrict__ x) {
    __shared__ float xs[TILE_T][PADA];   // xs[t][channel]
    const int b  = blockIdx.y;
    const int tc = blockIdx.x;
    const int tid = threadIdx.x;
    const int ty = tid >> 4, tx = tid & 15;
    const float* xb = x + (size_t)b * C_ * T_;
    const int t0 = tc * (TILES_PER * TILE_T);

    u64t acc[4][2];
#pragma unroll
    for (int i = 0; i < 4; ++i) { acc[i][0] = 0ull; acc[i][1] = 0ull; }

    float sxa = 0.f, sxb = 0.f;
    const int ca = tid >> 3;   // 0..31 (this thread loads channels ca and ca+32)
    const int tq = tid & 7;    // float4 slot within 32-t tile

    for (int tile = 0; tile < TILES_PER; ++tile) {
        const int tb = t0 + tile * TILE_T;
        float4 va = *(const float4*)(xb + (size_t)ca * T_ + tb + 4 * tq);
        float4 vb = *(const float4*)(xb + (size_t)(ca + 32) * T_ + tb + 4 * tq);
        sxa += va.x + va.y + va.z + va.w;
        sxb += vb.x + vb.y + vb.z + vb.w;

        __syncthreads();   // previous tile's compute done before overwrite
        xs[4 * tq + 0][ca] = va.x;  xs[4 * tq + 1][ca] = va.y;
        xs[4 * tq + 2][ca] = va.z;  xs[4 * tq + 3][ca] = va.w;
        xs[4 * tq + 0][ca + 32] = vb.x;  xs[4 * tq + 1][ca + 32] = vb.y;
        xs[4 * tq + 2][ca + 32] = vb.z;  xs[4 * tq + 3][ca + 32] = vb.w;
        __syncthreads();

#pragma unroll 8
        for (int t = 0; t < TILE_T; ++t) {
            float4 rv = *(const float4*)&xs[t][4 * ty];          // broadcast
            ulonglong2 cv = *(const ulonglong2*)&xs[t][4 * tx];  // 2 packed col pairs
            u64t r0 = fdup(rv.x), r1 = fdup(rv.y), r2 = fdup(rv.z), r3 = fdup(rv.w);
            ffma2(acc[0][0], r0, cv.x); ffma2(acc[0][1], r0, cv.y);
            ffma2(acc[1][0], r1, cv.x); ffma2(acc[1][1], r1, cv.y);
            ffma2(acc[2][0], r2, cv.x); ffma2(acc[2][1], r2, cv.y);
            ffma2(acc[3][0], r3, cv.x); ffma2(acc[3][1], r3, cv.y);
        }
    }

    // write 4x4 partial tile (coalesced float4 per row)
    float* gp = g_gp + ((size_t)(b * TCH + tc)) * (C_ * C_);
#pragma unroll
    for (int i = 0; i < 4; ++i) {
        float2 p0 = funp(acc[i][0]);
        float2 p1 = funp(acc[i][1]);
        float4 w = make_float4(p0.x, p0.y, p1.x, p1.y);
        *(float4*)(gp + (4 * ty + i) * C_ + 4 * tx) = w;
    }

    // reduce per-channel sums (reuse xs as scratch)
    __syncthreads();
    float* red = &xs[0][0];
    red[tid] = sxa;
    red[256 + tid] = sxb;
    __syncthreads();
    if (tid < 64) {
        const int base = (tid < 32) ? (8 * tid) : (256 + 8 * (tid - 32));
        float s = 0.f;
#pragma unroll
        for (int u = 0; u < 8; ++u) s += red[base + u];
        g_sxp[(b * TCH + tc) * C_ + tid] = s;
    }
}

// ---------------------------------------------------------------------------
// Kernel B: reduce partials, build E~[c][e] = S11*G + S21*sx[e],
// min-max normalize + softmax per row, store M row-major. Grid B_, 256 thr.
// ---------------------------------------------------------------------------
__global__ void __launch_bounds__(256) k_attn(const float* __restrict__ w1,
                                              const float* __restrict__ b1,
                                              const float* __restrict__ w2,
                                              const float* __restrict__ b2) {
    __shared__ float Es[C_][65];
    __shared__ float sxs[C_];
    const int b = blockIdx.x;
    const int tid = threadIdx.x;

    float S11 = 0.f, S21 = 0.f;
#pragma unroll
    for (int j = 0; j < 8; ++j) { S11 += w1[j] * w2[j]; S21 += b1[j] * w2[j]; }

    if (tid < 64) {
        float s = 0.f;
#pragma unroll
        for (int p = 0; p < TCH; ++p) s += g_sxp[(b * TCH + p) * C_ + tid];
        sxs[tid] = s;
    }
    __syncthreads();

    const float* gp = g_gp + (size_t)b * TCH * (C_ * C_);
    for (int i = tid; i < C_ * C_; i += 256) {
        float g = 0.f;
#pragma unroll
        for (int p = 0; p < TCH; ++p) g += gp[p * (C_ * C_) + i];
        const int e = i & 63;
        Es[i >> 6][e] = S11 * g + S21 * sxs[e];
    }
    __syncthreads();

    const int wid = tid >> 5, lane = tid & 31;
    float* at = g_at + (size_t)b * (C_ * C_);
    for (int r = wid; r < C_; r += 8) {
        float v0 = Es[r][lane], v1 = Es[r][lane + 32];
        float mx = fmaxf(v0, v1), mn = fminf(v0, v1);
#pragma unroll
        for (int o = 16; o; o >>= 1) {
            mx = fmaxf(mx, __shfl_xor_sync(0xffffffffu, mx, o));
            mn = fminf(mn, __shfl_xor_sync(0xffffffffu, mn, o));
        }
        const float inv = 1.f / (mx - mn + 1e-8f);
        const float nmax = (mx - mn) * inv;   // row max after normalization
        float e0 = expf((v0 - mn) * inv - nmax);
        float e1 = expf((v1 - mn) * inv - nmax);
        float s = e0 + e1;
#pragma unroll
        for (int o = 16; o; o >>= 1) s += __shfl_xor_sync(0xffffffffu, s, o);
        const float invs = 1.f / s;
        at[r * C_ + lane]      = e0 * invs;
        at[r * C_ + lane + 32] = e1 * invs;
    }
}

// ---------------------------------------------------------------------------
// Kernel C: out[c,t] = x[c,t] + gamma * sum_r M[r][c] * x[r][t].
// Grid (NCH_C, B_), 256 threads. Thread (ty,tx) in 16x16: 4 channels x 10 t
// (5 f32x2 pairs at t = 2*tx + 32*p). x-chunk reused from smem in epilogue.
// ---------------------------------------------------------------------------
__global__ void __launch_bounds__(256) k_apply(const float* __restrict__ x,
                                               const float* __restrict__ gptr,
                                               float* __restrict__ out) {
    extern __shared__ float dsm[];
    float* As  = dsm;                 // [64][66] padded attention
    float* xsc = dsm + C_ * 66;       // [64][160] x chunk
    const int b  = blockIdx.y;
    const int ck = blockIdx.x;
    const int t0 = ck * TC_C;
    const int tid = threadIdx.x;

    const float* at = g_at + (size_t)b * (C_ * C_);
    for (int i = tid; i < C_ * C_; i += 256)
        As[(i >> 6) * 66 + (i & 63)] = at[i];

    const float* xb = x + (size_t)b * C_ * T_;
#pragma unroll
    for (int k = 0; k < 10; ++k) {
        const int v = tid + k * 256;   // 0..2559 float4 slots
        const int e = v / 40, q = v % 40;
        *(float4*)&xsc[e * TC_C + 4 * q] =
            *(const float4*)(xb + (size_t)e * T_ + t0 + 4 * q);
    }
    __syncthreads();

    const int ty = tid >> 4, tx = tid & 15;
    u64t acc[4][5];
#pragma unroll
    for (int i = 0; i < 4; ++i)
#pragma unroll
        for (int p = 0; p < 5; ++p) acc[i][p] = 0ull;

    for (int r = 0; r < C_; ++r) {
        const float* arow = &As[r * 66 + 4 * ty];
        u64t a0 = fdup(arow[0]), a1 = fdup(arow[1]);
        u64t a2 = fdup(arow[2]), a3 = fdup(arow[3]);
        const float* xrow = &xsc[r * TC_C + 2 * tx];
#pragma unroll
        for (int p = 0; p < 5; ++p) {
            u64t xv = *(const u64t*)(xrow + 32 * p);
            ffma2(acc[0][p], a0, xv);
            ffma2(acc[1][p], a1, xv);
            ffma2(acc[2][p], a2, xv);
            ffma2(acc[3][p], a3, xv);
        }
    }

    const float gmv = *gptr;
    float* ob = out + (size_t)b * C_ * T_;
#pragma unroll
    for (int i = 0; i < 4; ++i) {
        const int c = 4 * ty + i;
#pragma unroll
        for (int p = 0; p < 5; ++p) {
            const int t = 2 * tx + 32 * p;
            float2 a = funp(acc[i][p]);
            const float xv0 = xsc[c * TC_C + t];
            const float xv1 = xsc[c * TC_C + t + 1];
            float2 o = make_float2(fmaf(gmv, a.x, xv0), fmaf(gmv, a.y, xv1));
            *(float2*)(ob + (size_t)c * T_ + t0 + t) = o;
        }
    }
}

// ---------------------------------------------------------------------------
extern "C" void kernel_launch(void* const* d_in, const int* in_sizes, int n_in,
                              void* d_out, int out_size) {
    const float* x  = (const float*)d_in[0];
    const float* w1 = (const float*)d_in[1];
    const float* b1 = (const float*)d_in[2];
    const float* w2 = (const float*)d_in[3];
    const float* b2 = (const float*)d_in[4];
    const float* gm = (const float*)d_in[5];
    float* out = (float*)d_out;

    const int smem_apply = (C_ * 66 + C_ * TC_C) * (int)sizeof(float);  // 57,856 B
    cudaFuncSetAttribute(k_apply, cudaFuncAttributeMaxDynamicSharedMemorySize, smem_apply);

    k_gram<<<dim3(TCH, B_), 256>>>(x);
    k_attn<<<B_, 256>>>(w1, b1, w2, b2);
    k_apply<<<dim3(NCH_C, B_), 256, smem_apply>>>(x, gm, out);
}